// round 16
// baseline (speedup 1.0000x reference)
#include <cuda_runtime.h>
#include <cooperative_groups.h>

namespace cg = cooperative_groups;

#define NSEQ 384
#define IND  350
#define G4   1024

// ---------------- scratch (device globals) -----------------------------------
__device__ float g_xT[IND * NSEQ];          // x transposed [350][384]
__device__ float g_gx[2][NSEQ][G4];         // gate preactivations (incl. biases)
__device__ float g_HT[512 * NSEQ];          // h transposed [512][384]
__device__ float g_ABp[2][NSEQ * 512];      // k-split partials of [384][A|B]

// ---------------- 1) embedding gather -> xT ----------------------------------
__global__ __launch_bounds__(352) void embed_kernel(
    const int* __restrict__ wid, const int* __restrict__ tyid,
    const float* __restrict__ etab, const float* __restrict__ ttab)
{
    int t = blockIdx.x, d = threadIdx.x;
    if (d < IND) {
        float v = (d < 300) ? etab[wid[t] * 300 + d]
                            : ttab[tyid[t] * 50 + (d - 300)];
        g_xT[d * NSEQ + t] = v;
    }
}

// ---------------- 2) gx = x @ Wih^T + bih + bhh (both dirs) -------------------
__global__ __launch_bounds__(384) void gx_kernel(
    const float* __restrict__ Wih_f, const float* __restrict__ bih_f, const float* __restrict__ bhh_f,
    const float* __restrict__ Wih_b, const float* __restrict__ bih_b, const float* __restrict__ bhh_b)
{
    int dir = blockIdx.y;
    const float* Wih = dir ? Wih_b : Wih_f;
    const float* bi  = dir ? bih_b : bih_f;
    const float* bh  = dir ? bhh_b : bhh_f;
    int t = threadIdx.x;
    int G0 = blockIdx.x * 8;
    const float* wp[8];
#pragma unroll
    for (int g = 0; g < 8; g++) wp[g] = Wih + (G0 + g) * IND;
    float acc[8] = {0.f,0.f,0.f,0.f,0.f,0.f,0.f,0.f};
    for (int k = 0; k < IND; k++) {
        float xv = g_xT[k * NSEQ + t];
#pragma unroll
        for (int g = 0; g < 8; g++) acc[g] = fmaf(xv, wp[g][k], acc[g]);
    }
#pragma unroll
    for (int g = 0; g < 8; g++)
        g_gx[dir][t][G0 + g] = acc[g] + bi[G0 + g] + bh[G0 + g];
}

// ---------------- fast activations -------------------------------------------
__device__ __forceinline__ float fast_sigmoid(float x) {
    return 1.f / (1.f + __expf(-x));
}
__device__ __forceinline__ float fast_tanh(float x) {
    return 1.f - 2.f / (__expf(2.f * x) + 1.f);
}

__device__ __forceinline__ void cluster_arrive_rel() {
    asm volatile("barrier.cluster.arrive.aligned;" ::: "memory");
}
__device__ __forceinline__ void cluster_wait_acq() {
    asm volatile("barrier.cluster.wait.aligned;" ::: "memory");
}

// ---------------- 4) BiLSTM: warp-local gate reduce (no psum/syncthreads) -----
// Lane map within each warp w (owning columns col = rk*32 + w*4 + cloc):
//   half = lane>>4, r = lane&15, gate = r>>2, cloc = r&3
//   each lane: 128-MAC half-row dot for gate-row G = gate*256 + col.
// Combine halves with shfl_xor(16); gather the 4 gate sums to writer lanes
// (half==0, gate==0) with 4 shfls. Gate math + DSMEM stores run in all 8
// warps' writer lanes. NO smem stage, NO __syncthreads inside the step.
__global__ void __cluster_dims__(8, 1, 1) __launch_bounds__(256, 1)
lstm_kernel(const float* __restrict__ Whh_f, const float* __restrict__ Whh_b)
{
    __shared__ __align__(16) float hb[2][256];

    cg::cluster_group cluster = cg::this_cluster();
    int rk  = (int)cluster.block_rank();
    int dir = blockIdx.x >> 3;
    const float* Whh = dir ? Whh_b : Whh_f;
    int tid  = threadIdx.x;
    int w    = tid >> 5, lane = tid & 31;
    int half = lane >> 4, r = lane & 15;
    int gate = r >> 2, cloc = r & 3;
    int col  = (rk << 5) + (w << 2) + cloc;   // 0..255 hidden column
    int G    = (gate << 8) + col;             // gate row in [0,1024)

    unsigned long long w2r[64];
    const float* wsrc = Whh + G * 256 + half * 128;
#pragma unroll
    for (int q = 0; q < 32; q++) {
        float4 v = *(const float4*)&wsrc[q * 4];
        asm("mov.b64 %0, {%1, %2};" : "=l"(w2r[2 * q])     : "f"(v.x), "f"(v.y));
        asm("mov.b64 %0, {%1, %2};" : "=l"(w2r[2 * q + 1]) : "f"(v.z), "f"(v.w));
    }
    hb[0][tid] = 0.f;
    float c = 0.f;
    bool writer = (half == 0) && (gate == 0);  // lanes 0..3 of each warp

    float* dsth[8];
    if (writer) {
#pragma unroll
        for (int pr = 0; pr < 8; pr++)
            dsth[pr] = cluster.map_shared_rank(&hb[0][0], pr);
    }
    __syncthreads();
    cluster.sync();          // hb[0] zeroed + visible cluster-wide

    const float* gx = &g_gx[dir][0][0];

    for (int t = 0; t < NSEQ; t++) {
        int cur = t & 1, nxt = cur ^ 1;
        int idx = dir ? (NSEQ - 1 - t) : t;

        float gxv0 = 0.f, gxv1 = 0.f, gxv2 = 0.f, gxv3 = 0.f;
        if (writer) {        // prefetch before barrier wait (off the chain)
            const float* gp = gx + idx * G4 + col;
            gxv0 = gp[0]; gxv1 = gp[256]; gxv2 = gp[512]; gxv3 = gp[768];
        }

        if (t > 0) cluster_wait_acq();   // h(t-1) now visible in hb[cur]

        const ulonglong2* h2 = (const ulonglong2*)&hb[cur][half * 128];
        unsigned long long a0 = 0ull, a1 = 0ull, a2 = 0ull, a3 = 0ull;
#pragma unroll
        for (int q = 0; q < 32; q += 2) {
            ulonglong2 hv0 = h2[q];
            ulonglong2 hv1 = h2[q + 1];
            asm("fma.rn.f32x2 %0, %1, %2, %0;" : "+l"(a0) : "l"(w2r[2*q]),   "l"(hv0.x));
            asm("fma.rn.f32x2 %0, %1, %2, %0;" : "+l"(a1) : "l"(w2r[2*q+1]), "l"(hv0.y));
            asm("fma.rn.f32x2 %0, %1, %2, %0;" : "+l"(a2) : "l"(w2r[2*q+2]), "l"(hv1.x));
            asm("fma.rn.f32x2 %0, %1, %2, %0;" : "+l"(a3) : "l"(w2r[2*q+3]), "l"(hv1.y));
        }
        float s0, s1, s2, s3, s4, s5, s6, s7;
        asm("mov.b64 {%0, %1}, %2;" : "=f"(s0), "=f"(s1) : "l"(a0));
        asm("mov.b64 {%0, %1}, %2;" : "=f"(s2), "=f"(s3) : "l"(a1));
        asm("mov.b64 {%0, %1}, %2;" : "=f"(s4), "=f"(s5) : "l"(a2));
        asm("mov.b64 {%0, %1}, %2;" : "=f"(s6), "=f"(s7) : "l"(a3));
        float sum = ((s0 + s1) + (s2 + s3)) + ((s4 + s5) + (s6 + s7));
        // combine halves: every lane now holds the full row-r dot
        sum += __shfl_xor_sync(0xffffffffu, sum, 16);
        // gather the 4 gate sums for this lane's column
        float fi = __shfl_sync(0xffffffffu, sum, cloc);
        float ff = __shfl_sync(0xffffffffu, sum, 4 + cloc);
        float fg = __shfl_sync(0xffffffffu, sum, 8 + cloc);
        float fo = __shfl_sync(0xffffffffu, sum, 12 + cloc);

        if (writer) {
            float iv = fast_sigmoid(fi + gxv0);
            float fv = fast_sigmoid(ff + gxv1);
            float gv = fast_tanh(fg + gxv2);
            float ov = fast_sigmoid(fo + gxv3);
            c = fv * c + iv * gv;
            float hn = ov * fast_tanh(c);
            if (t < NSEQ - 1) {
                int off = (nxt << 8) + col;
#pragma unroll
                for (int pr = 0; pr < 8; pr++) dsth[pr][off] = hn;
            }
            g_HT[(dir * 256 + col) * NSEQ + idx] = hn;
        }
        if (t < NSEQ - 1) cluster_arrive_rel();  // release writer stores
    }
    cluster.sync();   // no CTA exits while peers may still touch its smem
}

// ---------------- 5) A|B partials (IDENTICAL to passing R14) ------------------
__global__ __launch_bounds__(128) void ab_kernel(const float* __restrict__ W1)
{
    int t  = blockIdx.y * 128 + threadIdx.x;
    int f0 = blockIdx.x * 2;
    int kz = blockIdx.z;
    const float* wp[2];
#pragma unroll
    for (int g = 0; g < 2; g++) {
        int f = f0 + g;
        wp[g] = ((f < 256) ? (W1 + f * 1024) : (W1 + (f - 256) * 1024 + 512))
                + kz * 256;
    }
    const float* hp = &g_HT[(kz * 256) * NSEQ + t];
    float acc0 = 0.f, acc1 = 0.f;
#pragma unroll 8
    for (int k = 0; k < 256; k++) {
        float hv = hp[k * NSEQ];
        acc0 = fmaf(hv, wp[0][k], acc0);
        acc1 = fmaf(hv, wp[1][k], acc1);
    }
    g_ABp[kz][t * 512 + f0]     = acc0;
    g_ABp[kz][t * 512 + f0 + 1] = acc1;
}

// ---------------- 6) pair MLP via mma.sync tf32 (IDENTICAL to passing R14) ----
#define ZST   260
#define OF_Z  0                         // Z / Y  [128][260]
#define OF_W2 (128 * ZST)               // W2 chunk [32][260]
#define OF_WF (OF_W2 + 32 * ZST)        // Wf [16][260]
#define OF_A  (OF_WF + 16 * ZST)        // A_i + b1 [2][256]
#define OF_B2 (OF_A + 512)              // b2 [256]
#define P3_TOT ((OF_B2 + 256) * 4)      // 186112 bytes

__device__ __forceinline__ unsigned f2tf(float f) {
    unsigned r;
    asm("cvt.rna.tf32.f32 %0, %1;" : "=r"(r) : "f"(f));
    return r;
}
__device__ __forceinline__ float lky(float v) { return fmaxf(v, 0.01f * v); }

#define MMA_TF32(d, a0, a1, a2, a3, b0, b1)                                     \
    asm volatile("mma.sync.aligned.m16n8k8.row.col.f32.tf32.tf32.f32 "          \
                 "{%0,%1,%2,%3}, {%4,%5,%6,%7}, {%8,%9}, {%0,%1,%2,%3};"        \
                 : "+f"((d)[0]), "+f"((d)[1]), "+f"((d)[2]), "+f"((d)[3])       \
                 : "r"(a0), "r"(a1), "r"(a2), "r"(a3), "r"(b0), "r"(b1))

__global__ __launch_bounds__(256, 1) void pair3_kernel(
    const float* __restrict__ b1, const float* __restrict__ b2,
    const float* __restrict__ W2, const float* __restrict__ Wf,
    const float* __restrict__ bf, float* __restrict__ out)
{
    extern __shared__ __align__(16) float sm[];
    int tid = threadIdx.x, wid = tid >> 5, lane = tid & 31;
    int i0 = blockIdx.y * 2, j0 = blockIdx.x * 64;
    int lq = lane >> 2, lr = lane & 3;        // quad row / col within frag

    // stage A rows (+b1) from partials, b2, Wf
    sm[OF_A + tid]       = g_ABp[0][(i0 + 0) * 512 + tid]
                         + g_ABp[1][(i0 + 0) * 512 + tid] + b1[tid];
    sm[OF_A + 256 + tid] = g_ABp[0][(i0 + 1) * 512 + tid]
                         + g_ABp[1][(i0 + 1) * 512 + tid] + b1[tid];
    sm[OF_B2 + tid] = b2[tid];
#pragma unroll
    for (int it = 0; it < 16; it++) {
        int idx = tid + it * 256;             // 4096 = 16 rows x 256 k
        int r = idx >> 8, k = idx & 255;
        sm[OF_WF + r * ZST + k] = __uint_as_float(f2tf(Wf[r * 256 + k]));
    }
    __syncthreads();

    // build Z = tf32(leaky(A_ii + B_jj + b1))  [128][256]
#pragma unroll
    for (int it = 0; it < 32; it++) {
        int lin = tid + it * 256;             // 8192 float4
        int p = lin >> 6, k4 = (lin & 63) << 2;
        int ii = p >> 6, jj = p & 63;
        float4 bv0 = *(const float4*)&g_ABp[0][(j0 + jj) * 512 + 256 + k4];
        float4 bv1 = *(const float4*)&g_ABp[1][(j0 + jj) * 512 + 256 + k4];
        const float4 av = *(const float4*)&sm[OF_A + ii * 256 + k4];
        float4 z;
        z.x = __uint_as_float(f2tf(lky(av.x + bv0.x + bv1.x)));
        z.y = __uint_as_float(f2tf(lky(av.y + bv0.y + bv1.y)));
        z.z = __uint_as_float(f2tf(lky(av.z + bv0.z + bv1.z)));
        z.w = __uint_as_float(f2tf(lky(av.w + bv0.w + bv1.w)));
        *(float4*)&sm[OF_Z + p * ZST + k4] = z;
    }

    int mrow = wid * 16;
    float acc[128];                            // [ntile 32][4]
#pragma unroll
    for (int q = 0; q < 128; q++) acc[q] = 0.f;

    const unsigned* zp0 = (const unsigned*)&sm[OF_Z + (mrow + lq) * ZST + lr];
    const unsigned* zp1 = (const unsigned*)&sm[OF_Z + (mrow + 8 + lq) * ZST + lr];

#pragma unroll
    for (int nc = 0; nc < 8; nc++) {
        // load W2 chunk rows [nc*32, nc*32+32), tf32
#pragma unroll
        for (int it = 0; it < 8; it++) {
            int lin = tid + it * 256;          // 2048 float4
            int row = lin >> 6, k4 = (lin & 63) << 2;
            float4 v = *(const float4*)&W2[(nc * 32 + row) * 256 + k4];
            float4 w;
            w.x = __uint_as_float(f2tf(v.x)); w.y = __uint_as_float(f2tf(v.y));
            w.z = __uint_as_float(f2tf(v.z)); w.w = __uint_as_float(f2tf(v.w));
            *(float4*)&sm[OF_W2 + row * ZST + k4] = w;
        }
        __syncthreads();

        const unsigned* wp = (const unsigned*)&sm[OF_W2 + lq * ZST + lr];
        for (int k0 = 0; k0 < 256; k0 += 8) {
            unsigned a0 = zp0[k0], a1 = zp1[k0], a2 = zp0[k0 + 4], a3 = zp1[k0 + 4];
#pragma unroll
            for (int nt = 0; nt < 4; nt++) {
                unsigned bb0 = wp[nt * 8 * ZST + k0];
                unsigned bb1 = wp[nt * 8 * ZST + k0 + 4];
                MMA_TF32(&acc[(nc * 4 + nt) * 4], a0, a1, a2, a3, bb0, bb1);
            }
        }
        __syncthreads();
    }

    // epilogue: Y = tf32(leaky(D + b2)) over Z buffer
#pragma unroll
    for (int nt = 0; nt < 32; nt++) {
        int n0 = nt * 8 + 2 * lr;
        float bb0 = sm[OF_B2 + n0], bb1 = sm[OF_B2 + n0 + 1];
        sm[OF_Z + (mrow + lq) * ZST + n0]         = __uint_as_float(f2tf(lky(acc[nt*4+0] + bb0)));
        sm[OF_Z + (mrow + lq) * ZST + n0 + 1]     = __uint_as_float(f2tf(lky(acc[nt*4+1] + bb1)));
        sm[OF_Z + (mrow + 8 + lq) * ZST + n0]     = __uint_as_float(f2tf(lky(acc[nt*4+2] + bb0)));
        sm[OF_Z + (mrow + 8 + lq) * ZST + n0 + 1] = __uint_as_float(f2tf(lky(acc[nt*4+3] + bb1)));
    }
    __syncthreads();

    // GEMM2: out = Y @ Wf^T + bf   (N=16, K=256)
    float acc2[8];
#pragma unroll
    for (int q = 0; q < 8; q++) acc2[q] = 0.f;
    const unsigned* fp = (const unsigned*)&sm[OF_WF + lq * ZST + lr];
    for (int k0 = 0; k0 < 256; k0 += 8) {
        unsigned a0 = zp0[k0], a1 = zp1[k0], a2 = zp0[k0 + 4], a3 = zp1[k0 + 4];
#pragma unroll
        for (int nt = 0; nt < 2; nt++) {
            unsigned bb0 = fp[nt * 8 * ZST + k0];
            unsigned bb1 = fp[nt * 8 * ZST + k0 + 4];
            MMA_TF32(&acc2[nt * 4], a0, a1, a2, a3, bb0, bb1);
        }
    }
#pragma unroll
    for (int nt = 0; nt < 2; nt++) {
        int n0 = nt * 8 + 2 * lr;
        float bf0 = __ldg(&bf[n0]), bf1 = __ldg(&bf[n0 + 1]);
        int p = mrow + lq;
        int g0 = ((i0 + (p >> 6)) * NSEQ + j0 + (p & 63)) * 16;
        out[g0 + n0]     = acc2[nt * 4 + 0] + bf0;
        out[g0 + n0 + 1] = acc2[nt * 4 + 1] + bf1;
        int p2 = p + 8;
        int g1 = ((i0 + (p2 >> 6)) * NSEQ + j0 + (p2 & 63)) * 16;
        out[g1 + n0]     = acc2[nt * 4 + 2] + bf0;
        out[g1 + n0 + 1] = acc2[nt * 4 + 3] + bf1;
    }
}

// ---------------- launch ------------------------------------------------------
extern "C" void kernel_launch(void* const* d_in, const int* in_sizes, int n_in,
                              void* d_out, int out_size) {
    const int*   wid   = (const int*)d_in[0];
    const int*   tyid  = (const int*)d_in[1];
    const float* etab  = (const float*)d_in[2];
    const float* ttab  = (const float*)d_in[3];
    const float* Wih_f = (const float*)d_in[4];
    const float* Whh_f = (const float*)d_in[5];
    const float* bih_f = (const float*)d_in[6];
    const float* bhh_f = (const float*)d_in[7];
    const float* Wih_b = (const float*)d_in[8];
    const float* Whh_b = (const float*)d_in[9];
    const float* bih_b = (const float*)d_in[10];
    const float* bhh_b = (const float*)d_in[11];
    const float* W1    = (const float*)d_in[12];
    const float* b1    = (const float*)d_in[13];
    const float* W2    = (const float*)d_in[14];
    const float* b2    = (const float*)d_in[15];
    const float* Wf    = (const float*)d_in[16];
    const float* bf    = (const float*)d_in[17];
    float* out = (float*)d_out;

    cudaFuncSetAttribute(pair3_kernel,
                         cudaFuncAttributeMaxDynamicSharedMemorySize, P3_TOT);

    embed_kernel<<<NSEQ, 352>>>(wid, tyid, etab, ttab);
    gx_kernel<<<dim3(128, 2), 384>>>(Wih_f, bih_f, bhh_f, Wih_b, bih_b, bhh_b);
    lstm_kernel<<<16, 256>>>(Whh_f, Whh_b);
    ab_kernel<<<dim3(256, 3, 2), 128>>>(W1);
    pair3_kernel<<<dim3(6, 192), 256, P3_TOT>>>(b1, b2, W2, Wf, bf, out);
}

// round 17
// speedup vs baseline: 1.1674x; 1.1674x over previous
#include <cuda_runtime.h>
#include <cooperative_groups.h>

namespace cg = cooperative_groups;

#define NSEQ 384
#define IND  350
#define G4   1024

// ---------------- scratch (device globals) -----------------------------------
__device__ float g_xT[IND * NSEQ];          // x transposed [350][384]
__device__ float g_gx[2][NSEQ][G4];         // gate preactivations (incl. biases)
__device__ float g_HT[512 * NSEQ];          // h transposed [512][384]
__device__ float g_ABp[2][NSEQ * 512];      // k-split partials of [384][A|B]

// ---------------- 1) embedding gather -> xT ----------------------------------
__global__ __launch_bounds__(352) void embed_kernel(
    const int* __restrict__ wid, const int* __restrict__ tyid,
    const float* __restrict__ etab, const float* __restrict__ ttab)
{
    int t = blockIdx.x, d = threadIdx.x;
    if (d < IND) {
        float v = (d < 300) ? etab[wid[t] * 300 + d]
                            : ttab[tyid[t] * 50 + (d - 300)];
        g_xT[d * NSEQ + t] = v;
    }
}

// ---------------- 2) gx = x @ Wih^T + bih + bhh (both dirs) -------------------
__global__ __launch_bounds__(384) void gx_kernel(
    const float* __restrict__ Wih_f, const float* __restrict__ bih_f, const float* __restrict__ bhh_f,
    const float* __restrict__ Wih_b, const float* __restrict__ bih_b, const float* __restrict__ bhh_b)
{
    int dir = blockIdx.y;
    const float* Wih = dir ? Wih_b : Wih_f;
    const float* bi  = dir ? bih_b : bih_f;
    const float* bh  = dir ? bhh_b : bhh_f;
    int t = threadIdx.x;
    int G0 = blockIdx.x * 8;
    const float* wp[8];
#pragma unroll
    for (int g = 0; g < 8; g++) wp[g] = Wih + (G0 + g) * IND;
    float acc[8] = {0.f,0.f,0.f,0.f,0.f,0.f,0.f,0.f};
    for (int k = 0; k < IND; k++) {
        float xv = g_xT[k * NSEQ + t];
#pragma unroll
        for (int g = 0; g < 8; g++) acc[g] = fmaf(xv, wp[g][k], acc[g]);
    }
#pragma unroll
    for (int g = 0; g < 8; g++)
        g_gx[dir][t][G0 + g] = acc[g] + bi[G0 + g] + bh[G0 + g];
}

// ---------------- fast activations -------------------------------------------
__device__ __forceinline__ float fast_sigmoid(float x) {
    return 1.f / (1.f + __expf(-x));
}
__device__ __forceinline__ float fast_tanh(float x) {
    return 1.f - 2.f / (__expf(2.f * x) + 1.f);
}

__device__ __forceinline__ void cluster_arrive_rel() {
    asm volatile("barrier.cluster.arrive.aligned;" ::: "memory");
}
__device__ __forceinline__ void cluster_wait_acq() {
    asm volatile("barrier.cluster.wait.aligned;" ::: "memory");
}

// ---------------- 4) BiLSTM (IDENTICAL to passing R14) ------------------------
__global__ void __cluster_dims__(8, 1, 1) __launch_bounds__(256, 1)
lstm_kernel(const float* __restrict__ Whh_f, const float* __restrict__ Whh_b)
{
    __shared__ __align__(16) float hb[2][256];
    __shared__ __align__(16) float psum[256];

    cg::cluster_group cluster = cg::this_cluster();
    int rk  = (int)cluster.block_rank();
    int dir = blockIdx.x >> 3;
    const float* Whh = dir ? Whh_b : Whh_f;
    int tid  = threadIdx.x;
    int l    = tid & 127;
    int half = tid >> 7;
    int G    = ((l >> 5) << 8) + (rk << 5) + (l & 31);

    unsigned long long w2r[64];
    const float* wsrc = Whh + G * 256 + half * 128;
#pragma unroll
    for (int q = 0; q < 32; q++) {
        float4 v = *(const float4*)&wsrc[q * 4];
        asm("mov.b64 %0, {%1, %2};" : "=l"(w2r[2 * q])     : "f"(v.x), "f"(v.y));
        asm("mov.b64 %0, {%1, %2};" : "=l"(w2r[2 * q + 1]) : "f"(v.z), "f"(v.w));
    }
    hb[0][tid] = 0.f;
    float c = 0.f;

    float* dsth[8];
    if (tid < 32) {
#pragma unroll
        for (int pr = 0; pr < 8; pr++)
            dsth[pr] = cluster.map_shared_rank(&hb[0][0], pr);
    }
    __syncthreads();
    cluster.sync();          // hb[0] zeroed + visible cluster-wide

    const float* gx = &g_gx[dir][0][0];

    for (int t = 0; t < NSEQ; t++) {
        int cur = t & 1, nxt = cur ^ 1;
        int idx = dir ? (NSEQ - 1 - t) : t;

        float gxv0 = 0.f, gxv1 = 0.f, gxv2 = 0.f, gxv3 = 0.f;
        if (tid < 32) {  // prefetch issued BEFORE the barrier wait
            const float* gp = gx + idx * G4 + (rk << 5) + tid;
            gxv0 = gp[0]; gxv1 = gp[256]; gxv2 = gp[512]; gxv3 = gp[768];
        }

        if (t > 0) cluster_wait_acq();   // h(t-1) now visible in hb[cur]

        const ulonglong2* h2 = (const ulonglong2*)&hb[cur][half * 128];
        unsigned long long a0 = 0ull, a1 = 0ull, a2 = 0ull, a3 = 0ull;
#pragma unroll
        for (int q = 0; q < 32; q += 2) {
            ulonglong2 hv0 = h2[q];
            ulonglong2 hv1 = h2[q + 1];
            asm("fma.rn.f32x2 %0, %1, %2, %0;" : "+l"(a0) : "l"(w2r[2*q]),   "l"(hv0.x));
            asm("fma.rn.f32x2 %0, %1, %2, %0;" : "+l"(a1) : "l"(w2r[2*q+1]), "l"(hv0.y));
            asm("fma.rn.f32x2 %0, %1, %2, %0;" : "+l"(a2) : "l"(w2r[2*q+2]), "l"(hv1.x));
            asm("fma.rn.f32x2 %0, %1, %2, %0;" : "+l"(a3) : "l"(w2r[2*q+3]), "l"(hv1.y));
        }
        float s0, s1, s2, s3, s4, s5, s6, s7;
        asm("mov.b64 {%0, %1}, %2;" : "=f"(s0), "=f"(s1) : "l"(a0));
        asm("mov.b64 {%0, %1}, %2;" : "=f"(s2), "=f"(s3) : "l"(a1));
        asm("mov.b64 {%0, %1}, %2;" : "=f"(s4), "=f"(s5) : "l"(a2));
        asm("mov.b64 {%0, %1}, %2;" : "=f"(s6), "=f"(s7) : "l"(a3));
        psum[tid] = ((s0 + s1) + (s2 + s3)) + ((s4 + s5) + (s6 + s7));
        __syncthreads();

        if (tid < 32) {
            float ai = psum[tid]       + psum[128 + tid] + gxv0;
            float af = psum[32 + tid]  + psum[160 + tid] + gxv1;
            float ag = psum[64 + tid]  + psum[192 + tid] + gxv2;
            float ao = psum[96 + tid]  + psum[224 + tid] + gxv3;
            float iv = fast_sigmoid(ai);
            float fv = fast_sigmoid(af);
            float gv = fast_tanh(ag);
            float ov = fast_sigmoid(ao);
            c = fv * c + iv * gv;
            float hn = ov * fast_tanh(c);
            int col = (rk << 5) + tid;
            if (t < NSEQ - 1) {
                int off = (nxt << 8) + col;
#pragma unroll
                for (int pr = 0; pr < 8; pr++) dsth[pr][off] = hn;
            }
            g_HT[(dir * 256 + col) * NSEQ + idx] = hn;
        }
        if (t < NSEQ - 1) cluster_arrive_rel();  // release writer stores
    }
    cluster.sync();   // no CTA exits while peers may still touch its smem
}

// ---------------- 5) A|B partials (IDENTICAL to passing R14) ------------------
__global__ __launch_bounds__(128) void ab_kernel(const float* __restrict__ W1)
{
    int t  = blockIdx.y * 128 + threadIdx.x;
    int f0 = blockIdx.x * 2;
    int kz = blockIdx.z;
    const float* wp[2];
#pragma unroll
    for (int g = 0; g < 2; g++) {
        int f = f0 + g;
        wp[g] = ((f < 256) ? (W1 + f * 1024) : (W1 + (f - 256) * 1024 + 512))
                + kz * 256;
    }
    const float* hp = &g_HT[(kz * 256) * NSEQ + t];
    float acc0 = 0.f, acc1 = 0.f;
#pragma unroll 8
    for (int k = 0; k < 256; k++) {
        float hv = hp[k * NSEQ];
        acc0 = fmaf(hv, wp[0][k], acc0);
        acc1 = fmaf(hv, wp[1][k], acc1);
    }
    g_ABp[kz][t * 512 + f0]     = acc0;
    g_ABp[kz][t * 512 + f0 + 1] = acc1;
}

// ---------------- 6) pair MLP: R14 structure + register-staged W2 prefetch ----
#define ZST   260
#define OF_Z  0                         // Z / Y  [128][260]
#define OF_W2 (128 * ZST)               // W2 chunk [32][260]
#define OF_WF (OF_W2 + 32 * ZST)        // Wf [16][260]
#define OF_A  (OF_WF + 16 * ZST)        // A_i + b1 [2][256]
#define OF_B2 (OF_A + 512)              // b2 [256]
#define P3_TOT ((OF_B2 + 256) * 4)      // 186112 bytes (proven size)

__device__ __forceinline__ unsigned f2tf(float f) {
    unsigned r;
    asm("cvt.rna.tf32.f32 %0, %1;" : "=r"(r) : "f"(f));
    return r;
}
__device__ __forceinline__ float lky(float v) { return fmaxf(v, 0.01f * v); }

#define MMA_TF32(d, a0, a1, a2, a3, b0, b1)                                     \
    asm volatile("mma.sync.aligned.m16n8k8.row.col.f32.tf32.tf32.f32 "          \
                 "{%0,%1,%2,%3}, {%4,%5,%6,%7}, {%8,%9}, {%0,%1,%2,%3};"        \
                 : "+f"((d)[0]), "+f"((d)[1]), "+f"((d)[2]), "+f"((d)[3])       \
                 : "r"(a0), "r"(a1), "r"(a2), "r"(a3), "r"(b0), "r"(b1))

__global__ __launch_bounds__(256, 1) void pair3_kernel(
    const float* __restrict__ b1, const float* __restrict__ b2,
    const float* __restrict__ W2, const float* __restrict__ Wf,
    const float* __restrict__ bf, float* __restrict__ out)
{
    extern __shared__ __align__(16) float sm[];
    int tid = threadIdx.x, wid = tid >> 5, lane = tid & 31;
    int i0 = blockIdx.y * 2, j0 = blockIdx.x * 64;
    int lq = lane >> 2, lr = lane & 3;        // quad row / col within frag

    // per-thread W2 staging coordinates (8 float4 tiles per chunk)
    int wrow[8], wk4[8];
#pragma unroll
    for (int it = 0; it < 8; it++) {
        int lin = tid + it * 256;              // 2048 float4
        wrow[it] = lin >> 6; wk4[it] = (lin & 63) << 2;
    }

    // stage A rows (+b1) from partials, b2, Wf; prefetch W2 chunk 0 into regs
    float4 pre[8];
#pragma unroll
    for (int it = 0; it < 8; it++)
        pre[it] = *(const float4*)&W2[wrow[it] * 256 + wk4[it]];

    sm[OF_A + tid]       = g_ABp[0][(i0 + 0) * 512 + tid]
                         + g_ABp[1][(i0 + 0) * 512 + tid] + b1[tid];
    sm[OF_A + 256 + tid] = g_ABp[0][(i0 + 1) * 512 + tid]
                         + g_ABp[1][(i0 + 1) * 512 + tid] + b1[tid];
    sm[OF_B2 + tid] = b2[tid];
#pragma unroll
    for (int it = 0; it < 16; it++) {
        int idx = tid + it * 256;             // 4096 = 16 rows x 256 k
        int r = idx >> 8, k = idx & 255;
        sm[OF_WF + r * ZST + k] = __uint_as_float(f2tf(Wf[r * 256 + k]));
    }
    __syncthreads();

    // build Z = tf32(leaky(A_ii + B_jj + b1))  [128][256]
#pragma unroll
    for (int it = 0; it < 32; it++) {
        int lin = tid + it * 256;             // 8192 float4
        int p = lin >> 6, k4 = (lin & 63) << 2;
        int ii = p >> 6, jj = p & 63;
        float4 bv0 = *(const float4*)&g_ABp[0][(j0 + jj) * 512 + 256 + k4];
        float4 bv1 = *(const float4*)&g_ABp[1][(j0 + jj) * 512 + 256 + k4];
        const float4 av = *(const float4*)&sm[OF_A + ii * 256 + k4];
        float4 z;
        z.x = __uint_as_float(f2tf(lky(av.x + bv0.x + bv1.x)));
        z.y = __uint_as_float(f2tf(lky(av.y + bv0.y + bv1.y)));
        z.z = __uint_as_float(f2tf(lky(av.z + bv0.z + bv1.z)));
        z.w = __uint_as_float(f2tf(lky(av.w + bv0.w + bv1.w)));
        *(float4*)&sm[OF_Z + p * ZST + k4] = z;
    }

    int mrow = wid * 16;
    float acc[128];                            // [ntile 32][4]
#pragma unroll
    for (int q = 0; q < 128; q++) acc[q] = 0.f;

    const unsigned* zp0 = (const unsigned*)&sm[OF_Z + (mrow + lq) * ZST + lr];
    const unsigned* zp1 = (const unsigned*)&sm[OF_Z + (mrow + 8 + lq) * ZST + lr];

#pragma unroll
    for (int nc = 0; nc < 8; nc++) {
        // store staged chunk nc (regs -> tf32 smem)
#pragma unroll
        for (int it = 0; it < 8; it++) {
            float4 w;
            w.x = __uint_as_float(f2tf(pre[it].x));
            w.y = __uint_as_float(f2tf(pre[it].y));
            w.z = __uint_as_float(f2tf(pre[it].z));
            w.w = __uint_as_float(f2tf(pre[it].w));
            *(float4*)&sm[OF_W2 + wrow[it] * ZST + wk4[it]] = w;
        }
        __syncthreads();
        // issue chunk nc+1 loads NOW; latency hidden under the MMA block
        if (nc < 7) {
#pragma unroll
            for (int it = 0; it < 8; it++)
                pre[it] = *(const float4*)&W2[((nc + 1) * 32 + wrow[it]) * 256 + wk4[it]];
        }
        const unsigned* wp = (const unsigned*)&sm[OF_W2 + lq * ZST + lr];
        for (int k0 = 0; k0 < 256; k0 += 8) {
            unsigned a0 = zp0[k0], a1 = zp1[k0], a2 = zp0[k0 + 4], a3 = zp1[k0 + 4];
#pragma unroll
            for (int nt = 0; nt < 4; nt++) {
                unsigned bb0 = wp[nt * 8 * ZST + k0];
                unsigned bb1 = wp[nt * 8 * ZST + k0 + 4];
                MMA_TF32(&acc[(nc * 4 + nt) * 4], a0, a1, a2, a3, bb0, bb1);
            }
        }
        __syncthreads();
    }

    // epilogue: Y = tf32(leaky(D + b2)) over Z buffer
#pragma unroll
    for (int nt = 0; nt < 32; nt++) {
        int n0 = nt * 8 + 2 * lr;
        float bb0 = sm[OF_B2 + n0], bb1 = sm[OF_B2 + n0 + 1];
        sm[OF_Z + (mrow + lq) * ZST + n0]         = __uint_as_float(f2tf(lky(acc[nt*4+0] + bb0)));
        sm[OF_Z + (mrow + lq) * ZST + n0 + 1]     = __uint_as_float(f2tf(lky(acc[nt*4+1] + bb1)));
        sm[OF_Z + (mrow + 8 + lq) * ZST + n0]     = __uint_as_float(f2tf(lky(acc[nt*4+2] + bb0)));
        sm[OF_Z + (mrow + 8 + lq) * ZST + n0 + 1] = __uint_as_float(f2tf(lky(acc[nt*4+3] + bb1)));
    }
    __syncthreads();

    // GEMM2: out = Y @ Wf^T + bf   (N=16, K=256)
    float acc2[8];
#pragma unroll
    for (int q = 0; q < 8; q++) acc2[q] = 0.f;
    const unsigned* fp = (const unsigned*)&sm[OF_WF + lq * ZST + lr];
    for (int k0 = 0; k0 < 256; k0 += 8) {
        unsigned a0 = zp0[k0], a1 = zp1[k0], a2 = zp0[k0 + 4], a3 = zp1[k0 + 4];
#pragma unroll
        for (int nt = 0; nt < 2; nt++) {
            unsigned bb0 = fp[nt * 8 * ZST + k0];
            unsigned bb1 = fp[nt * 8 * ZST + k0 + 4];
            MMA_TF32(&acc2[nt * 4], a0, a1, a2, a3, bb0, bb1);
        }
    }
#pragma unroll
    for (int nt = 0; nt < 2; nt++) {
        int n0 = nt * 8 + 2 * lr;
        float bf0 = __ldg(&bf[n0]), bf1 = __ldg(&bf[n0 + 1]);
        int p = mrow + lq;
        int g0 = ((i0 + (p >> 6)) * NSEQ + j0 + (p & 63)) * 16;
        out[g0 + n0]     = acc2[nt * 4 + 0] + bf0;
        out[g0 + n0 + 1] = acc2[nt * 4 + 1] + bf1;
        int p2 = p + 8;
        int g1 = ((i0 + (p2 >> 6)) * NSEQ + j0 + (p2 & 63)) * 16;
        out[g1 + n0]     = acc2[nt * 4 + 2] + bf0;
        out[g1 + n0 + 1] = acc2[nt * 4 + 3] + bf1;
    }
}

// ---------------- launch ------------------------------------------------------
extern "C" void kernel_launch(void* const* d_in, const int* in_sizes, int n_in,
                              void* d_out, int out_size) {
    const int*   wid   = (const int*)d_in[0];
    const int*   tyid  = (const int*)d_in[1];
    const float* etab  = (const float*)d_in[2];
    const float* ttab  = (const float*)d_in[3];
    const float* Wih_f = (const float*)d_in[4];
    const float* Whh_f = (const float*)d_in[5];
    const float* bih_f = (const float*)d_in[6];
    const float* bhh_f = (const float*)d_in[7];
    const float* Wih_b = (const float*)d_in[8];
    const float* Whh_b = (const float*)d_in[9];
    const float* bih_b = (const float*)d_in[10];
    const float* bhh_b = (const float*)d_in[11];
    const float* W1    = (const float*)d_in[12];
    const float* b1    = (const float*)d_in[13];
    const float* W2    = (const float*)d_in[14];
    const float* b2    = (const float*)d_in[15];
    const float* Wf    = (const float*)d_in[16];
    const float* bf    = (const float*)d_in[17];
    float* out = (float*)d_out;

    cudaFuncSetAttribute(pair3_kernel,
                         cudaFuncAttributeMaxDynamicSharedMemorySize, P3_TOT);

    embed_kernel<<<NSEQ, 352>>>(wid, tyid, etab, ttab);
    gx_kernel<<<dim3(128, 2), 384>>>(Wih_f, bih_f, bhh_f, Wih_b, bih_b, bhh_b);
    lstm_kernel<<<16, 256>>>(Whh_f, Whh_b);
    ab_kernel<<<dim3(256, 3, 2), 128>>>(W1);
    pair3_kernel<<<dim3(6, 192), 256, P3_TOT>>>(b1, b2, W2, Wf, bf, out);
}